// round 1
// baseline (speedup 1.0000x reference)
#include <cuda_runtime.h>
#include <math.h>

// Problem dims
#define BB   1024
#define IND  256
#define LATD 512
#define HIDD 1024
#define OUTD 64
#define NSTEPS 20

// Scratch (device globals — no allocation allowed)
__device__ float g_h[BB * LATD];     // current state h
__device__ float g_htmp[BB * LATD];  // dyn input (h + c*k)
__device__ float g_G[BB * HIDD];     // tanh intermediate
__device__ float g_acc[BB * LATD];   // RK4 k-accumulator

#define BM 64
#define BN 64
#define BK 16

// EPI modes:
// 0: C = tanh(v + bias + b2s*bias2)                      (h0 and gemm1)
// 1: k = v+bias; acc = k;       htmp = hbase + cstep*k   (k1)
// 2: k = v+bias; acc += wk*k;   htmp = hbase + cstep*k   (k2,k3)
// 3: k = v+bias; hn = hbase + s6*(acc+k); C = hn; htmp = hn  (k4 + state update)
// 4: C = v + bias                                        (output projection)
template <int EPI>
__global__ __launch_bounds__(256) void gemm_k(
    const float* __restrict__ A, int lda,
    const float* __restrict__ W, int N,          // W is K x N row-major, ldw == N
    const float* __restrict__ bias,
    const float* __restrict__ bias2, float b2s,
    float* __restrict__ C, int ldc,
    float* __restrict__ accb,
    const float* __restrict__ hbase,
    float* __restrict__ htmp,
    float wk, float cstep, float s6,
    int K)
{
    __shared__ float As[BK][BM + 4];   // +4 pad: 16B-aligned rows, conflict-free STS
    __shared__ float Bs[BK][BN];

    const int bm0 = blockIdx.y * BM;
    const int bn0 = blockIdx.x * BN;
    const int tid = threadIdx.x;
    const int tx = tid & 15;          // 0..15 -> n micro-tile
    const int ty = tid >> 4;          // 0..15 -> m micro-tile
    const int arow = tid >> 2;        // 0..63
    const int akq  = (tid & 3) << 2;  // 0,4,8,12
    const int brow = tid >> 4;        // 0..15
    const int bcol = (tid & 15) << 2; // 0..60

    const float* Aptr = A + (size_t)(bm0 + arow) * lda + akq;
    const float* Wptr = W + (size_t)brow * N + bn0 + bcol;

    float acc[4][4];
#pragma unroll
    for (int i = 0; i < 4; i++)
#pragma unroll
        for (int j = 0; j < 4; j++) acc[i][j] = 0.0f;

    for (int k0 = 0; k0 < K; k0 += BK) {
        float4 av = *reinterpret_cast<const float4*>(Aptr + k0);
        float4 bv = *reinterpret_cast<const float4*>(Wptr + (size_t)k0 * N);

        As[akq + 0][arow] = av.x;
        As[akq + 1][arow] = av.y;
        As[akq + 2][arow] = av.z;
        As[akq + 3][arow] = av.w;
        *reinterpret_cast<float4*>(&Bs[brow][bcol]) = bv;
        __syncthreads();

#pragma unroll
        for (int kk = 0; kk < BK; kk++) {
            float4 a = *reinterpret_cast<const float4*>(&As[kk][ty << 2]);
            float4 b = *reinterpret_cast<const float4*>(&Bs[kk][tx << 2]);
            acc[0][0] += a.x * b.x; acc[0][1] += a.x * b.y; acc[0][2] += a.x * b.z; acc[0][3] += a.x * b.w;
            acc[1][0] += a.y * b.x; acc[1][1] += a.y * b.y; acc[1][2] += a.y * b.z; acc[1][3] += a.y * b.w;
            acc[2][0] += a.z * b.x; acc[2][1] += a.z * b.y; acc[2][2] += a.z * b.z; acc[2][3] += a.z * b.w;
            acc[3][0] += a.w * b.x; acc[3][1] += a.w * b.y; acc[3][2] += a.w * b.z; acc[3][3] += a.w * b.w;
        }
        __syncthreads();
    }

#pragma unroll
    for (int i = 0; i < 4; i++) {
        const int m = bm0 + (ty << 2) + i;
#pragma unroll
        for (int j = 0; j < 4; j++) {
            const int n = bn0 + (tx << 2) + j;
            float v = acc[i][j];
            if (EPI == 0) {
                v += bias[n] + b2s * bias2[n];
                C[(size_t)m * ldc + n] = tanhf(v);
            } else if (EPI == 4) {
                C[(size_t)m * ldc + n] = v + bias[n];
            } else {
                const float kval = v + bias[n];
                const size_t idx = (size_t)m * ldc + n;
                if (EPI == 1) {
                    accb[idx] = kval;
                    htmp[idx] = hbase[idx] + cstep * kval;
                } else if (EPI == 2) {
                    accb[idx] += wk * kval;
                    htmp[idx] = hbase[idx] + cstep * kval;
                } else { // EPI == 3
                    const float hn = hbase[idx] + s6 * (accb[idx] + kval);
                    C[idx] = hn;     // C == g_h (in-place state update)
                    htmp[idx] = hn;
                }
            }
        }
    }
}

extern "C" void kernel_launch(void* const* d_in, const int* in_sizes, int n_in,
                              void* d_out, int out_size)
{
    const float* x     = (const float*)d_in[0];
    const float* W_in  = (const float*)d_in[1];
    const float* b_in  = (const float*)d_in[2];
    const float* W1    = (const float*)d_in[3];  // (513, 1024)
    const float* b1    = (const float*)d_in[4];
    const float* W2    = (const float*)d_in[5];  // (1024, 512)
    const float* b2    = (const float*)d_in[6];
    const float* W_out = (const float*)d_in[7];  // (256, 64)
    const float* b_out = (const float*)d_in[8];
    float* out = (float*)d_out;

    float *h, *htmp, *G, *accp;
    cudaGetSymbolAddress((void**)&h,    g_h);
    cudaGetSymbolAddress((void**)&htmp, g_htmp);
    cudaGetSymbolAddress((void**)&G,    g_G);
    cudaGetSymbolAddress((void**)&accp, g_acc);

    const float dt = (1.0f - 0.0f) / (float)NSTEPS;
    const float s6 = dt / 6.0f;
    const float* W1t = W1 + (size_t)LATD * HIDD;  // last row of W1 (the time column weights)

    const dim3 blk(256);
    const dim3 gr_h0(LATD / BN, BB / BM);    // (8,16)
    const dim3 gr_g1(HIDD / BN, BB / BM);    // (16,16)
    const dim3 gr_g2(LATD / BN, BB / BM);    // (8,16)
    const dim3 gr_out(OUTD / BN, BB / BM);   // (1,16)

    // h0 = tanh(x @ W_in + b_in)  -> g_h
    gemm_k<0><<<gr_h0, blk>>>(x, IND, W_in, LATD, b_in, b_in, 0.0f,
                              h, LATD, nullptr, nullptr, nullptr,
                              0.0f, 0.0f, 0.0f, IND);

    for (int step = 0; step < NSTEPS; step++) {
        const float t = dt * (float)step;
        const float tsub[4]  = {t, t + 0.5f * dt, t + 0.5f * dt, t + dt};
        const float csub[4]  = {0.5f * dt, 0.5f * dt, dt, 0.0f};
        const float wsub[4]  = {1.0f, 2.0f, 2.0f, 1.0f};

        for (int sub = 0; sub < 4; sub++) {
            const float* dynin = (sub == 0) ? h : htmp;
            // G = tanh(dynin @ W1[:512] + b1 + tsub * W1[512,:])
            gemm_k<0><<<gr_g1, blk>>>(dynin, LATD, W1, HIDD, b1, W1t, tsub[sub],
                                      G, HIDD, nullptr, nullptr, nullptr,
                                      0.0f, 0.0f, 0.0f, LATD);
            // k = G @ W2 + b2, fused RK4 bookkeeping
            if (sub == 0) {
                gemm_k<1><<<gr_g2, blk>>>(G, HIDD, W2, LATD, b2, b2, 0.0f,
                                          nullptr, LATD, accp, h, htmp,
                                          1.0f, csub[sub], s6, HIDD);
            } else if (sub < 3) {
                gemm_k<2><<<gr_g2, blk>>>(G, HIDD, W2, LATD, b2, b2, 0.0f,
                                          nullptr, LATD, accp, h, htmp,
                                          wsub[sub], csub[sub], s6, HIDD);
            } else {
                gemm_k<3><<<gr_g2, blk>>>(G, HIDD, W2, LATD, b2, b2, 0.0f,
                                          h, LATD, accp, h, htmp,
                                          1.0f, 0.0f, s6, HIDD);
            }
        }
    }

    // out = h[:, :256] @ W_out + b_out
    gemm_k<4><<<gr_out, blk>>>(h, LATD, W_out, OUTD, b_out, b_out, 0.0f,
                               out, OUTD, nullptr, nullptr, nullptr,
                               0.0f, 0.0f, 0.0f, LATD / 2);
}

// round 12
// speedup vs baseline: 2.0602x; 2.0602x over previous
#include <cuda_runtime.h>
#include <cuda_bf16.h>
#include <math.h>
#include <stdint.h>

#define BB   1024
#define IND  256
#define LATD 512
#define HIDD 1024
#define OUTD 64
#define NSTEPS 20

#define BM 128
#define BN 64
#define BK 32
#define BKP 40          // padded row length in bf16 (80 bytes/row)
#define THREADS 256

// ---------------- device scratch (no allocation allowed) ----------------
__device__ float g_h[BB * LATD];
__device__ float g_acc[BB * LATD];
__device__ __nv_bfloat16 g_xh[BB * IND],  g_xl[BB * IND];
__device__ __nv_bfloat16 g_hh[BB * LATD], g_hl[BB * LATD];
__device__ __nv_bfloat16 g_th[BB * LATD], g_tl[BB * LATD];
__device__ __nv_bfloat16 g_Gh[BB * HIDD], g_Gl[BB * HIDD];
__device__ __nv_bfloat16 g_W1h[HIDD * LATD], g_W1l[HIDD * LATD];   // [N=1024, K=512]
__device__ __nv_bfloat16 g_W2h[LATD * HIDD], g_W2l[LATD * HIDD];   // [N=512,  K=1024]
__device__ __nv_bfloat16 g_Wih[LATD * IND],  g_Wil[LATD * IND];    // [N=512,  K=256]
__device__ __nv_bfloat16 g_Woh[OUTD * (LATD/2)], g_Wol[OUTD * (LATD/2)]; // [64,256]

__device__ __forceinline__ uint32_t smem_u32(const void* p) {
    uint32_t a;
    asm("{ .reg .u64 t; cvta.to.shared.u64 t, %1; cvt.u32.u64 %0, t; }" : "=r"(a) : "l"(p));
    return a;
}

#define LDMX4(r0, r1, r2, r3, addr)                                               \
    asm volatile("ldmatrix.sync.aligned.m8n8.x4.shared.b16 {%0,%1,%2,%3}, [%4];"  \
        : "=r"(r0), "=r"(r1), "=r"(r2), "=r"(r3) : "r"(addr))

#define MMA16816(d, a, b0v, b1v)                                                  \
    asm volatile("mma.sync.aligned.m16n8k16.row.col.f32.bf16.bf16.f32 "           \
        "{%0,%1,%2,%3}, {%4,%5,%6,%7}, {%8,%9}, {%0,%1,%2,%3};"                   \
        : "+f"((d)[0]), "+f"((d)[1]), "+f"((d)[2]), "+f"((d)[3])                  \
        : "r"((a)[0]), "r"((a)[1]), "r"((a)[2]), "r"((a)[3]), "r"(b0v), "r"(b1v))

// ---------------- SMEM layout (dynamic, 61440 B) ----------------
#define AS_B (BM * BKP * 2)   // 10240
#define BS_B (BN * BKP * 2)   // 5120
#define SM_AH(s) ((s) * AS_B)
#define SM_AL(s) (2 * AS_B + (s) * AS_B)
#define SM_BH(s) (4 * AS_B + (s) * BS_B)
#define SM_BL(s) (4 * AS_B + 2 * BS_B + (s) * BS_B)
#define SMEM_TOTAL (4 * AS_B + 4 * BS_B)

__device__ __forceinline__ void store_split(__nv_bfloat16* Oh, __nv_bfloat16* Ol,
                                            size_t idx, float a, float b) {
    __nv_bfloat16 ah = __float2bfloat16(a);
    __nv_bfloat16 bh = __float2bfloat16(b);
    __nv_bfloat162 hv; hv.x = ah; hv.y = bh;
    *reinterpret_cast<__nv_bfloat162*>(Oh + idx) = hv;
    __nv_bfloat162 lv;
    lv.x = __float2bfloat16(a - __bfloat162float(ah));
    lv.y = __float2bfloat16(b - __bfloat162float(bh));
    *reinterpret_cast<__nv_bfloat162*>(Ol + idx) = lv;
}

// EPI modes:
// 0: val = tanh(v + bias + b2s*bias2); Cf opt; split -> Oh/Ol
// 1: k = v+bias; acc = k;       val = hbase + cstep*k; split
// 2: k = v+bias; acc += wk*k;   val = hbase + cstep*k; split
// 3: k = v+bias; val = hbase + s6*(acc+k); Cf = val; split
// 4: Cf = v + bias
template <int EPI>
__device__ __forceinline__ void epi_pair(int m, int n, float v0, float v1,
    const float* __restrict__ bias, const float* __restrict__ bias2, float b2s,
    float* __restrict__ Cf, int ldc,
    __nv_bfloat16* __restrict__ Oh, __nv_bfloat16* __restrict__ Ol, int ldo,
    float* __restrict__ accb, const float* __restrict__ hbase,
    float wk, float cstep, float s6)
{
    if (EPI == 0) {
        v0 = tanhf(v0 + bias[n]     + b2s * bias2[n]);
        v1 = tanhf(v1 + bias[n + 1] + b2s * bias2[n + 1]);
        if (Cf) {
            float2 f; f.x = v0; f.y = v1;
            *reinterpret_cast<float2*>(Cf + (size_t)m * ldc + n) = f;
        }
        store_split(Oh, Ol, (size_t)m * ldo + n, v0, v1);
    } else if (EPI == 4) {
        float2 f; f.x = v0 + bias[n]; f.y = v1 + bias[n + 1];
        *reinterpret_cast<float2*>(Cf + (size_t)m * ldc + n) = f;
    } else {
        const size_t idx = (size_t)m * ldo + n;
        const float k0v = v0 + bias[n];
        const float k1v = v1 + bias[n + 1];
        float a0, a1;
        if (EPI == 1) { a0 = k0v; a1 = k1v; accb[idx] = a0; accb[idx + 1] = a1; }
        else          { a0 = accb[idx] + wk * k0v; a1 = accb[idx + 1] + wk * k1v;
                        if (EPI == 2) { accb[idx] = a0; accb[idx + 1] = a1; } }
        const float h0v = hbase[idx], h1v = hbase[idx + 1];
        float o0, o1;
        if (EPI == 3) {
            o0 = h0v + s6 * a0;
            o1 = h1v + s6 * a1;
            float2 f; f.x = o0; f.y = o1;
            *reinterpret_cast<float2*>(Cf + idx) = f;
        } else {
            o0 = h0v + cstep * k0v;
            o1 = h1v + cstep * k1v;
        }
        store_split(Oh, Ol, idx, o0, o1);
    }
}

template <int EPI>
__global__ __launch_bounds__(THREADS)
void mma_gemm(const __nv_bfloat16* __restrict__ Ah, const __nv_bfloat16* __restrict__ Al,
              int lda, int K,
              const __nv_bfloat16* __restrict__ Bh, const __nv_bfloat16* __restrict__ Bl,
              const float* __restrict__ bias, const float* __restrict__ bias2, float b2s,
              float* __restrict__ Cf, int ldc,
              __nv_bfloat16* __restrict__ Oh, __nv_bfloat16* __restrict__ Ol, int ldo,
              float* __restrict__ accb, const float* __restrict__ hbase,
              float wk, float cstep, float s6)
{
    extern __shared__ char smem[];
    const uint32_t sb = smem_u32(smem);
    const int tid = threadIdx.x;
    const int wid = tid >> 5, lane = tid & 31;
    const int wm = (wid & 3) * 32;          // warp M offset within block
    const int wn = (wid >> 2) * 32;         // warp N offset within block
    const int lgrp = lane >> 3, lrow = lane & 7;
    const int bm0 = blockIdx.y * BM, bn0 = blockIdx.x * BN;

    float acc[2][4][4];
#pragma unroll
    for (int i = 0; i < 2; i++)
#pragma unroll
        for (int j = 0; j < 4; j++)
#pragma unroll
            for (int k = 0; k < 4; k++) acc[i][j][k] = 0.0f;

    // staging slot mapping
    const int arow0 = tid >> 2,        akq0 = (tid & 3);          // A slot i=0
    const int arow1 = (tid + 256) >> 2, akq1 = (tid & 3);         // A slot i=1 (rows 64..127)
    const int brow  = tid >> 2,        bkq  = (tid & 3);          // B slot

    // ---- load chunk 0 into stage 0 ----
    {
        const int k0 = 0;
        uint4 a0h = *reinterpret_cast<const uint4*>(Ah + (size_t)(bm0 + arow0) * lda + k0 + akq0 * 8);
        uint4 a0l = *reinterpret_cast<const uint4*>(Al + (size_t)(bm0 + arow0) * lda + k0 + akq0 * 8);
        uint4 a1h = *reinterpret_cast<const uint4*>(Ah + (size_t)(bm0 + arow1) * lda + k0 + akq1 * 8);
        uint4 a1l = *reinterpret_cast<const uint4*>(Al + (size_t)(bm0 + arow1) * lda + k0 + akq1 * 8);
        uint4 b_h = *reinterpret_cast<const uint4*>(Bh + (size_t)(bn0 + brow) * K + k0 + bkq * 8);
        uint4 b_l = *reinterpret_cast<const uint4*>(Bl + (size_t)(bn0 + brow) * K + k0 + bkq * 8);
        *reinterpret_cast<uint4*>(smem + SM_AH(0) + arow0 * 80 + akq0 * 16) = a0h;
        *reinterpret_cast<uint4*>(smem + SM_AL(0) + arow0 * 80 + akq0 * 16) = a0l;
        *reinterpret_cast<uint4*>(smem + SM_AH(0) + arow1 * 80 + akq1 * 16) = a1h;
        *reinterpret_cast<uint4*>(smem + SM_AL(0) + arow1 * 80 + akq1 * 16) = a1l;
        *reinterpret_cast<uint4*>(smem + SM_BH(0) + brow * 80 + bkq * 16) = b_h;
        *reinterpret_cast<uint4*>(smem + SM_BL(0) + brow * 80 + bkq * 16) = b_l;
    }
    __syncthreads();

    const int nc = K / BK;
    for (int c = 0; c < nc; c++) {
        const int s = c & 1;
        const bool pre = (c + 1 < nc);
        uint4 a0h, a0l, a1h, a1l, b_h, b_l;
        if (pre) {
            const int k0 = (c + 1) * BK;
            a0h = *reinterpret_cast<const uint4*>(Ah + (size_t)(bm0 + arow0) * lda + k0 + akq0 * 8);
            a0l = *reinterpret_cast<const uint4*>(Al + (size_t)(bm0 + arow0) * lda + k0 + akq0 * 8);
            a1h = *reinterpret_cast<const uint4*>(Ah + (size_t)(bm0 + arow1) * lda + k0 + akq1 * 8);
            a1l = *reinterpret_cast<const uint4*>(Al + (size_t)(bm0 + arow1) * lda + k0 + akq1 * 8);
            b_h = *reinterpret_cast<const uint4*>(Bh + (size_t)(bn0 + brow) * K + k0 + bkq * 8);
            b_l = *reinterpret_cast<const uint4*>(Bl + (size_t)(bn0 + brow) * K + k0 + bkq * 8);
        }

        // ---- compute on stage s ----
#pragma unroll
        for (int ks = 0; ks < 2; ks++) {
            uint32_t ahf[2][4], alf[2][4], bhf[2][4], blf[2][4];
            const int acol = (ks * 16 + (lgrp >> 1) * 8) * 2;
            const int bcol = (ks * 16 + (lgrp & 1) * 8) * 2;
#pragma unroll
            for (int mt = 0; mt < 2; mt++) {
                const int ar = wm + mt * 16 + (lgrp & 1) * 8 + lrow;
                uint32_t adh = sb + SM_AH(s) + ar * 80 + acol;
                uint32_t adl = sb + SM_AL(s) + ar * 80 + acol;
                LDMX4(ahf[mt][0], ahf[mt][1], ahf[mt][2], ahf[mt][3], adh);
                LDMX4(alf[mt][0], alf[mt][1], alf[mt][2], alf[mt][3], adl);
            }
#pragma unroll
            for (int ng = 0; ng < 2; ng++) {
                const int br = wn + ng * 16 + (lgrp >> 1) * 8 + lrow;
                uint32_t bdh = sb + SM_BH(s) + br * 80 + bcol;
                uint32_t bdl = sb + SM_BL(s) + br * 80 + bcol;
                LDMX4(bhf[ng][0], bhf[ng][1], bhf[ng][2], bhf[ng][3], bdh);
                LDMX4(blf[ng][0], blf[ng][1], blf[ng][2], blf[ng][3], bdl);
            }
#pragma unroll
            for (int mt = 0; mt < 2; mt++)
#pragma unroll
                for (int nt = 0; nt < 4; nt++) {
                    const int ng = nt >> 1, o = (nt & 1) * 2;
                    MMA16816(acc[mt][nt], ahf[mt], bhf[ng][o], bhf[ng][o + 1]);
                    MMA16816(acc[mt][nt], ahf[mt], blf[ng][o], blf[ng][o + 1]);
                    MMA16816(acc[mt][nt], alf[mt], bhf[ng][o], bhf[ng][o + 1]);
                }
        }

        if (pre) {
            const int sn = s ^ 1;
            *reinterpret_cast<uint4*>(smem + SM_AH(sn) + arow0 * 80 + akq0 * 16) = a0h;
            *reinterpret_cast<uint4*>(smem + SM_AL(sn) + arow0 * 80 + akq0 * 16) = a0l;
            *reinterpret_cast<uint4*>(smem + SM_AH(sn) + arow1 * 80 + akq1 * 16) = a1h;
            *reinterpret_cast<uint4*>(smem + SM_AL(sn) + arow1 * 80 + akq1 * 16) = a1l;
            *reinterpret_cast<uint4*>(smem + SM_BH(sn) + brow * 80 + bkq * 16) = b_h;
            *reinterpret_cast<uint4*>(smem + SM_BL(sn) + brow * 80 + bkq * 16) = b_l;
        }
        __syncthreads();
    }

    // ---- epilogue ----
#pragma unroll
    for (int mt = 0; mt < 2; mt++)
#pragma unroll
        for (int nt = 0; nt < 4; nt++) {
            const int m0 = bm0 + wm + mt * 16 + (lane >> 2);
            const int n  = bn0 + wn + nt * 8 + (lane & 3) * 2;
            epi_pair<EPI>(m0,     n, acc[mt][nt][0], acc[mt][nt][1],
                          bias, bias2, b2s, Cf, ldc, Oh, Ol, ldo, accb, hbase, wk, cstep, s6);
            epi_pair<EPI>(m0 + 8, n, acc[mt][nt][2], acc[mt][nt][3],
                          bias, bias2, b2s, Cf, ldc, Oh, Ol, ldo, accb, hbase, wk, cstep, s6);
        }
}

// ---------------- prep kernels ----------------
__global__ void k_split(const float* __restrict__ src,
                        __nv_bfloat16* __restrict__ h, __nv_bfloat16* __restrict__ l, int n) {
    int i = blockIdx.x * blockDim.x + threadIdx.x;
    if (i < n) {
        float v = src[i];
        __nv_bfloat16 hi = __float2bfloat16(v);
        h[i] = hi;
        l[i] = __float2bfloat16(v - __bfloat162float(hi));
    }
}
__global__ void k_splitT(const float* __restrict__ W, int K, int N,
                         __nv_bfloat16* __restrict__ Th, __nv_bfloat16* __restrict__ Tl) {
    int i = blockIdx.x * blockDim.x + threadIdx.x;
    if (i < K * N) {
        int k = i / N, n = i - k * N;
        float v = W[i];
        __nv_bfloat16 hi = __float2bfloat16(v);
        Th[(size_t)n * K + k] = hi;
        Tl[(size_t)n * K + k] = __float2bfloat16(v - __bfloat162float(hi));
    }
}

// ---------------- host ----------------
extern "C" void kernel_launch(void* const* d_in, const int* in_sizes, int n_in,
                              void* d_out, int out_size)
{
    const float* x     = (const float*)d_in[0];
    const float* W_in  = (const float*)d_in[1];
    const float* b_in  = (const float*)d_in[2];
    const float* W1    = (const float*)d_in[3];  // (513, 1024)
    const float* b1    = (const float*)d_in[4];
    const float* W2    = (const float*)d_in[5];  // (1024, 512)
    const float* b2    = (const float*)d_in[6];
    const float* W_out = (const float*)d_in[7];  // (256, 64)
    const float* b_out = (const float*)d_in[8];
    float* out = (float*)d_out;

    cudaFuncSetAttribute(mma_gemm<0>, cudaFuncAttributeMaxDynamicSharedMemorySize, SMEM_TOTAL);
    cudaFuncSetAttribute(mma_gemm<1>, cudaFuncAttributeMaxDynamicSharedMemorySize, SMEM_TOTAL);
    cudaFuncSetAttribute(mma_gemm<2>, cudaFuncAttributeMaxDynamicSharedMemorySize, SMEM_TOTAL);
    cudaFuncSetAttribute(mma_gemm<3>, cudaFuncAttributeMaxDynamicSharedMemorySize, SMEM_TOTAL);
    cudaFuncSetAttribute(mma_gemm<4>, cudaFuncAttributeMaxDynamicSharedMemorySize, SMEM_TOTAL);

    float *h, *acc;
    __nv_bfloat16 *xh, *xl, *hh, *hl, *th, *tl, *Gh, *Gl;
    __nv_bfloat16 *W1h, *W1l, *W2h, *W2l, *Wih, *Wil, *Woh, *Wol;
    cudaGetSymbolAddress((void**)&h,   g_h);
    cudaGetSymbolAddress((void**)&acc, g_acc);
    cudaGetSymbolAddress((void**)&xh,  g_xh);  cudaGetSymbolAddress((void**)&xl,  g_xl);
    cudaGetSymbolAddress((void**)&hh,  g_hh);  cudaGetSymbolAddress((void**)&hl,  g_hl);
    cudaGetSymbolAddress((void**)&th,  g_th);  cudaGetSymbolAddress((void**)&tl,  g_tl);
    cudaGetSymbolAddress((void**)&Gh,  g_Gh);  cudaGetSymbolAddress((void**)&Gl,  g_Gl);
    cudaGetSymbolAddress((void**)&W1h, g_W1h); cudaGetSymbolAddress((void**)&W1l, g_W1l);
    cudaGetSymbolAddress((void**)&W2h, g_W2h); cudaGetSymbolAddress((void**)&W2l, g_W2l);
    cudaGetSymbolAddress((void**)&Wih, g_Wih); cudaGetSymbolAddress((void**)&Wil, g_Wil);
    cudaGetSymbolAddress((void**)&Woh, g_Woh); cudaGetSymbolAddress((void**)&Wol, g_Wol);

    const float dt = 1.0f / (float)NSTEPS;
    const float s6 = dt / 6.0f;
    const float* W1t = W1 + (size_t)LATD * HIDD;  // fp32 time-column weights (row 512)

    // prep: split inputs / split+transpose weights
    k_split<<<(BB * IND + 255) / 256, 256>>>(x, xh, xl, BB * IND);
    k_splitT<<<(IND * LATD + 255) / 256, 256>>>(W_in, IND, LATD, Wih, Wil);
    k_splitT<<<(LATD * HIDD + 255) / 256, 256>>>(W1, LATD, HIDD, W1h, W1l);
    k_splitT<<<(HIDD * LATD + 255) / 256, 256>>>(W2, HIDD, LATD, W2h, W2l);
    k_splitT<<<((LATD / 2) * OUTD + 255) / 256, 256>>>(W_out, LATD / 2, OUTD, Woh, Wol);

    const dim3 blk(THREADS);
    const dim3 gr_h0(LATD / BN, BB / BM);   // (8, 8)
    const dim3 gr_g1(HIDD / BN, BB / BM);   // (16, 8)
    const dim3 gr_g2(LATD / BN, BB / BM);   // (8, 8)
    const dim3 gr_out(OUTD / BN, BB / BM);  // (1, 8)

    // h0 = tanh(x @ W_in + b_in) -> h (fp32) + (hh, hl)
    mma_gemm<0><<<gr_h0, blk, SMEM_TOTAL>>>(xh, xl, IND, IND, Wih, Wil,
        b_in, b_in, 0.0f, h, LATD, hh, hl, LATD, nullptr, nullptr, 0.f, 0.f, 0.f);

    for (int step = 0; step < NSTEPS; step++) {
        const float t = dt * (float)step;
        const float tsub[4] = {t, t + 0.5f * dt, t + 0.5f * dt, t + dt};
        const float csub[4] = {0.5f * dt, 0.5f * dt, dt, 0.0f};
        const float wsub[4] = {1.0f, 2.0f, 2.0f, 1.0f};

        for (int sub = 0; sub < 4; sub++) {
            const __nv_bfloat16* dih = (sub == 0) ? hh : th;
            const __nv_bfloat16* dil = (sub == 0) ? hl : tl;
            // G = tanh(dyn_in @ W1[:512] + b1 + t*W1[512,:]) -> (Gh, Gl)
            mma_gemm<0><<<gr_g1, blk, SMEM_TOTAL>>>(dih, dil, LATD, LATD, W1h, W1l,
                b1, W1t, tsub[sub], nullptr, 0, Gh, Gl, HIDD, nullptr, nullptr, 0.f, 0.f, 0.f);
            // k = G @ W2 + b2 with fused RK4 bookkeeping
            if (sub == 0) {
                mma_gemm<1><<<gr_g2, blk, SMEM_TOTAL>>>(Gh, Gl, HIDD, HIDD, W2h, W2l,
                    b2, b2, 0.f, nullptr, 0, th, tl, LATD, acc, h, 1.0f, csub[0], s6);
            } else if (sub < 3) {
                mma_gemm<2><<<gr_g2, blk, SMEM_TOTAL>>>(Gh, Gl, HIDD, HIDD, W2h, W2l,
                    b2, b2, 0.f, nullptr, 0, th, tl, LATD, acc, h, wsub[sub], csub[sub], s6);
            } else {
                mma_gemm<3><<<gr_g2, blk, SMEM_TOTAL>>>(Gh, Gl, HIDD, HIDD, W2h, W2l,
                    b2, b2, 0.f, h, LATD, hh, hl, LATD, acc, h, 1.0f, 0.f, s6);
            }
        }
    }

    // out = h[:, :256] @ W_out + b_out
    mma_gemm<4><<<gr_out, blk, SMEM_TOTAL>>>(hh, hl, LATD, LATD / 2, Woh, Wol,
        b_out, b_out, 0.f, out, OUTD, nullptr, nullptr, 0, nullptr, nullptr, 0.f, 0.f, 0.f);
}